// round 3
// baseline (speedup 1.0000x reference)
#include <cuda_runtime.h>
#include <cuda_bf16.h>
#include <math.h>

#define S_LEN 2048
#define DE    4096
#define HQ    32
#define HKV   8
#define DH    128

// ---------------- scratch (no allocations allowed) ----------------
__device__ float g_q[S_LEN * HQ  * DH];   // 32 MB, [s][h][d], pre-scaled by 1/sqrt(DH)
__device__ float g_k[S_LEN * HKV * DH];   //  8 MB, [s][kh][d]
__device__ float g_v[S_LEN * HKV * DH];   //  8 MB, [s][kh][d]
__device__ float g_o[S_LEN * HQ  * DH];   // 32 MB, [s][h][d]

// =================================================================
// Classic double-buffered fp32 SGEMM: C[M,N] = A[M,K] @ B[K,N]
// A,B,C row-major. M%128==0, N%128==0, K%16==0 (all true here).
// 256 threads, 8x8 per-thread tile.
// =================================================================
__global__ __launch_bounds__(256) void sgemm_kernel(
    const float* __restrict__ A, const float* __restrict__ B,
    float* __restrict__ C, int M, int N, int K)
{
    constexpr int BM = 128, BN = 128, BK = 16, BMP = 132; // BMP: padded A-tile stride
    __shared__ float As[2][BK][BMP];
    __shared__ float Bs[2][BK][BN];

    const int tid = threadIdx.x;
    const int tx  = tid & 15;   // 0..15 -> N
    const int ty  = tid >> 4;   // 0..15 -> M
    const long row0 = (long)blockIdx.y * BM;
    const long col0 = (long)blockIdx.x * BN;

    const float* Aa = A + row0 * K;
    const float* Bb = B + col0;

    float acc[8][8];
#pragma unroll
    for (int m = 0; m < 8; m++)
#pragma unroll
        for (int n = 0; n < 8; n++) acc[m][n] = 0.f;

    const int KT = K / BK;

    // prologue: tile 0 -> buf 0
#pragma unroll
    for (int t = 0; t < 2; t++) {
        int idx = tid + t * 256;            // 0..511
        int r = idx >> 2, c4 = (idx & 3) << 2;
        float4 v = *(const float4*)(Aa + (long)r * K + c4);
        As[0][c4 + 0][r] = v.x; As[0][c4 + 1][r] = v.y;
        As[0][c4 + 2][r] = v.z; As[0][c4 + 3][r] = v.w;
    }
#pragma unroll
    for (int t = 0; t < 2; t++) {
        int idx = tid + t * 256;
        int r = idx >> 5, c4 = (idx & 31) << 2;
        *(float4*)&Bs[0][r][c4] = *(const float4*)(Bb + (long)r * N + c4);
    }
    __syncthreads();

    int buf = 0;
    for (int kt = 0; kt < KT; kt++) {
        float4 la[2], lb[2];
        const bool has_next = (kt + 1 < KT);
        if (has_next) {
            const int k0 = (kt + 1) * BK;
#pragma unroll
            for (int t = 0; t < 2; t++) {
                int idx = tid + t * 256;
                int r = idx >> 2, c4 = (idx & 3) << 2;
                la[t] = *(const float4*)(Aa + (long)r * K + k0 + c4);
            }
#pragma unroll
            for (int t = 0; t < 2; t++) {
                int idx = tid + t * 256;
                int r = idx >> 5, c4 = (idx & 31) << 2;
                lb[t] = *(const float4*)(Bb + (long)(k0 + r) * N + c4);
            }
        }
#pragma unroll
        for (int k = 0; k < BK; k++) {
            float regM[8], regN[8];
            *(float4*)&regM[0] = *(const float4*)&As[buf][k][ty * 8];
            *(float4*)&regM[4] = *(const float4*)&As[buf][k][ty * 8 + 4];
            *(float4*)&regN[0] = *(const float4*)&Bs[buf][k][tx * 8];
            *(float4*)&regN[4] = *(const float4*)&Bs[buf][k][tx * 8 + 4];
#pragma unroll
            for (int m = 0; m < 8; m++)
#pragma unroll
                for (int n = 0; n < 8; n++)
                    acc[m][n] = fmaf(regM[m], regN[n], acc[m][n]);
        }
        if (has_next) {
            const int nb = buf ^ 1;
#pragma unroll
            for (int t = 0; t < 2; t++) {
                int idx = tid + t * 256;
                int r = idx >> 2, c4 = (idx & 3) << 2;
                As[nb][c4 + 0][r] = la[t].x; As[nb][c4 + 1][r] = la[t].y;
                As[nb][c4 + 2][r] = la[t].z; As[nb][c4 + 3][r] = la[t].w;
            }
#pragma unroll
            for (int t = 0; t < 2; t++) {
                int idx = tid + t * 256;
                int r = idx >> 5, c4 = (idx & 31) << 2;
                *(float4*)&Bs[nb][r][c4] = lb[t];
            }
        }
        __syncthreads();
        buf ^= 1;
    }

#pragma unroll
    for (int m = 0; m < 8; m++) {
        long row = row0 + ty * 8 + m;
        float* Cp = C + row * N + col0 + tx * 8;
        *(float4*)Cp       = make_float4(acc[m][0], acc[m][1], acc[m][2], acc[m][3]);
        *(float4*)(Cp + 4) = make_float4(acc[m][4], acc[m][5], acc[m][6], acc[m][7]);
    }
}

// =================================================================
// RoPE (reference convention: y1 = x1*c + x2*s; y2 = -x1*s + x2*c),
// applied in-place to g_q (with attention scale folded in) and g_k.
// =================================================================
__global__ void rope_kernel(const float* __restrict__ cs)
{
    const int total = S_LEN * (HQ + HKV) * (DH / 2);
    int idx = blockIdx.x * blockDim.x + threadIdx.x;
    if (idx >= total) return;
    const int d = idx & 63;
    const int h = (idx >> 6) % (HQ + HKV);
    const int s = idx / (64 * (HQ + HKV));

    const float c  = cs[s * 64 + d];
    const float sn = cs[S_LEN * 64 + s * 64 + d];

    float* base;
    float sc;
    if (h < HQ) { base = g_q + ((long)s * HQ + h) * DH;         sc = 0.08838834764831845f; } // 1/sqrt(128)
    else        { base = g_k + ((long)s * HKV + (h - HQ)) * DH; sc = 1.0f; }

    const float x1 = base[d], x2 = base[d + 64];
    base[d]      = (x1 * c + x2 * sn) * sc;
    base[d + 64] = (-x1 * sn + x2 * c) * sc;
}

// =================================================================
// Causal flash attention, fp32. One block = (64 q rows, one q head).
// 256 threads: tx = tid&15, ty = tid>>4 (4-row group).
// Score tile per thread: 4 rows x 4 cols (j = tx*4+n, 64 cols total).
// PV tile per thread:    4 rows x 8 d-cols (d = tx*8+n, 128 total).
// Dynamic smem: Qs[64][132] | Kt[128][68] | Vs[64][132] | Ps[64][68]
// NOTE: Kt row stride MUST be a multiple of 4 (float4 reads at d*stride+tx*4).
// =================================================================
#define KT_STRIDE 68
#define FLASH_SMEM ((64*132 + 128*KT_STRIDE + 64*132 + 64*68) * 4)

__global__ __launch_bounds__(256, 1) void flash_kernel()
{
    extern __shared__ float sm[];
    float* Qs = sm;                       // 64 x 132
    float* Kt = Qs + 64 * 132;            // 128 x 68  (K transposed: [d][j])
    float* Vs = Kt + 128 * KT_STRIDE;     // 64 x 132
    float* Ps = Vs + 64 * 132;            // 64 x 68   (P: [i][j])

    const int tid = threadIdx.x;
    const int tx  = tid & 15;
    const int ty  = tid >> 4;
    const int qt  = gridDim.x - 1 - blockIdx.x;  // longest blocks first
    const int h   = blockIdx.y;
    const int kvh = h >> 2;                      // G = 4
    const int q0  = qt * 64;

    // load Q tile (pre-scaled, post-RoPE)
#pragma unroll
    for (int t = 0; t < 8; t++) {
        int idx = tid + t * 256;          // 0..2047
        int r = idx >> 5;
        int c4 = (idx & 31) << 2;
        float4 v = *(const float4*)(g_q + ((long)(q0 + r) * HQ + h) * DH + c4);
        *(float4*)&Qs[r * 132 + c4] = v;
    }

    float m_i[4], l_i[4], o_acc[4][8];
#pragma unroll
    for (int m = 0; m < 4; m++) {
        m_i[m] = -INFINITY; l_i[m] = 0.f;
#pragma unroll
        for (int n = 0; n < 8; n++) o_acc[m][n] = 0.f;
    }

    for (int kt = 0; kt <= qt; kt++) {
        __syncthreads();                  // prev PV done before overwrite
        const int k0 = kt * 64;
#pragma unroll
        for (int t = 0; t < 8; t++) {
            int idx = tid + t * 256;
            int r = idx >> 5;
            int c4 = (idx & 31) << 2;
            float4 kvv = *(const float4*)(g_k + ((long)(k0 + r) * HKV + kvh) * DH + c4);
            Kt[(c4 + 0) * KT_STRIDE + r] = kvv.x;
            Kt[(c4 + 1) * KT_STRIDE + r] = kvv.y;
            Kt[(c4 + 2) * KT_STRIDE + r] = kvv.z;
            Kt[(c4 + 3) * KT_STRIDE + r] = kvv.w;
            float4 vv = *(const float4*)(g_v + ((long)(k0 + r) * HKV + kvh) * DH + c4);
            *(float4*)&Vs[r * 132 + c4] = vv;
        }
        __syncthreads();

        // ---- scores: S(4x4 per thread) = Q(row) . K(col), cols j = tx*4+n ----
        float sacc[4][4];
#pragma unroll
        for (int m = 0; m < 4; m++)
#pragma unroll
            for (int n = 0; n < 4; n++) sacc[m][n] = 0.f;

        float qbuf[4][4];
#pragma unroll 2
        for (int d4 = 0; d4 < 32; d4++) {
#pragma unroll
            for (int m = 0; m < 4; m++)
                *(float4*)qbuf[m] = *(const float4*)&Qs[(ty * 4 + m) * 132 + d4 * 4];
#pragma unroll
            for (int e = 0; e < 4; e++) {
                const int d = d4 * 4 + e;
                float kn[4];
                *(float4*)kn = *(const float4*)&Kt[d * KT_STRIDE + tx * 4];
#pragma unroll
                for (int m = 0; m < 4; m++)
#pragma unroll
                    for (int n = 0; n < 4; n++)
                        sacc[m][n] = fmaf(qbuf[m][e], kn[n], sacc[m][n]);
            }
        }

        // ---- online softmax (per row; 16 lanes with same ty share a row) ----
        const bool diag = (kt == qt);
#pragma unroll
        for (int m = 0; m < 4; m++) {
            const int ig = ty * 4 + m;    // local row; global col j = k0 + tx*4+n
            if (diag) {
#pragma unroll
                for (int n = 0; n < 4; n++)
                    if (tx * 4 + n > ig) sacc[m][n] = -INFINITY;
            }
            float mx = sacc[m][0];
#pragma unroll
            for (int n = 1; n < 4; n++) mx = fmaxf(mx, sacc[m][n]);
#pragma unroll
            for (int off = 8; off >= 1; off >>= 1)
                mx = fmaxf(mx, __shfl_xor_sync(0xffffffffu, mx, off));
            const float mnew = fmaxf(m_i[m], mx);
            const float alpha = __expf(m_i[m] - mnew);

            float rsum = 0.f;
#pragma unroll
            for (int n = 0; n < 4; n++) {
                float p = __expf(sacc[m][n] - mnew);
                sacc[m][n] = p;
                rsum += p;
            }
#pragma unroll
            for (int off = 8; off >= 1; off >>= 1)
                rsum += __shfl_xor_sync(0xffffffffu, rsum, off);

            l_i[m] = l_i[m] * alpha + rsum;
            m_i[m] = mnew;
#pragma unroll
            for (int n = 0; n < 8; n++) o_acc[m][n] *= alpha;

            *(float4*)&Ps[ig * 68 + tx * 4] =
                make_float4(sacc[m][0], sacc[m][1], sacc[m][2], sacc[m][3]);
        }
        __syncthreads();                  // Ps visible to everyone

        // ---- PV: O(4x8 per thread) += P(row,j) * V(j,d), d = tx*8+n ----
#pragma unroll 4
        for (int j = 0; j < 64; j++) {
            float pm[4];
#pragma unroll
            for (int m = 0; m < 4; m++) pm[m] = Ps[(ty * 4 + m) * 68 + j];
            float vn[8];
            const float* vp = &Vs[j * 132 + tx * 8];
            *(float4*)&vn[0] = *(const float4*)vp;
            *(float4*)&vn[4] = *(const float4*)(vp + 4);
#pragma unroll
            for (int m = 0; m < 4; m++)
#pragma unroll
                for (int n = 0; n < 8; n++)
                    o_acc[m][n] = fmaf(pm[m], vn[n], o_acc[m][n]);
        }
    }

    // epilogue: normalize and write
#pragma unroll
    for (int m = 0; m < 4; m++) {
        const float inv = 1.0f / l_i[m];
        const int row = q0 + ty * 4 + m;
        float* op = g_o + ((long)row * HQ + h) * DH + tx * 8;
        *(float4*)op       = make_float4(o_acc[m][0] * inv, o_acc[m][1] * inv,
                                         o_acc[m][2] * inv, o_acc[m][3] * inv);
        *(float4*)(op + 4) = make_float4(o_acc[m][4] * inv, o_acc[m][5] * inv,
                                         o_acc[m][6] * inv, o_acc[m][7] * inv);
    }
}

// =================================================================
extern "C" void kernel_launch(void* const* d_in, const int* in_sizes, int n_in,
                              void* d_out, int out_size)
{
    const float* x  = (const float*)d_in[0];
    const float* cs = (const float*)d_in[1];
    const float* wq = (const float*)d_in[2];
    const float* wk = (const float*)d_in[3];
    const float* wv = (const float*)d_in[4];
    const float* wo = (const float*)d_in[5];
    float* out = (float*)d_out;

    float *q, *k, *v, *o;
    cudaGetSymbolAddress((void**)&q, g_q);
    cudaGetSymbolAddress((void**)&k, g_k);
    cudaGetSymbolAddress((void**)&v, g_v);
    cudaGetSymbolAddress((void**)&o, g_o);

    cudaFuncSetAttribute((const void*)flash_kernel,
                         cudaFuncAttributeMaxDynamicSharedMemorySize, FLASH_SMEM);

    // QKV projections
    sgemm_kernel<<<dim3(DE / 128, S_LEN / 128), 256>>>(x, wq, q, S_LEN, DE, DE);
    sgemm_kernel<<<dim3((HKV * DH) / 128, S_LEN / 128), 256>>>(x, wk, k, S_LEN, HKV * DH, DE);
    sgemm_kernel<<<dim3((HKV * DH) / 128, S_LEN / 128), 256>>>(x, wv, v, S_LEN, HKV * DH, DE);

    // RoPE (+ fold 1/sqrt(DH) into q)
    const int rope_total = S_LEN * (HQ + HKV) * (DH / 2);
    rope_kernel<<<(rope_total + 255) / 256, 256>>>(cs);

    // causal flash attention
    flash_kernel<<<dim3(S_LEN / 64, HQ), 256, FLASH_SMEM>>>();

    // output projection
    sgemm_kernel<<<dim3(DE / 128, S_LEN / 128), 256>>>(o, wo, out, S_LEN, DE, DE);
}

// round 5
// speedup vs baseline: 1.6847x; 1.6847x over previous
#include <cuda_runtime.h>
#include <cuda_bf16.h>
#include <cstdint>
#include <math.h>

#define S_LEN 2048
#define DE    4096
#define HQ    32
#define HKV   8
#define DH    128

// ---------------- scratch (no allocations allowed) ----------------
__device__ float g_q[S_LEN * HQ  * DH];   // 32 MB, [s][h][d], pre-scaled by 1/sqrt(DH)
__device__ float g_k[S_LEN * HKV * DH];   //  8 MB, [s][kh][d]
__device__ float g_v[S_LEN * HKV * DH];   //  8 MB, [s][kh][d]
__device__ float g_o[S_LEN * HQ  * DH];   // 32 MB, [s][h][d]

// =================================================================
// bf16x3 tensor-core GEMM: C[M,N] = A[M,K] @ B[K,N], all fp32 in gmem.
// Each fp32 is split on the fly into bf16 hi+lo; C ~= Ah*Bh + Ah*Bl + Al*Bh.
// Error ~2^-17 (lo*lo dropped). mma.sync m16n8k16, fp32 accum.
// CTA tile 128x128x32, 256 threads (8 warps, 2m x 4n), warp tile 64x32.
// Requires M%128==0, N%128==0, K%32==0.
// =================================================================
#define BKP 34              // padded k-stride (bf16 units) for smem planes
#define PLANE (128 * BKP)   // 4352 bf16 per plane
#define STAGE_ELEMS (4 * PLANE)
#define GEMM_SMEM (2 * STAGE_ELEMS * 2)  // bytes = 69632

#define MMA16816(d, a, b)                                              \
    asm volatile(                                                      \
        "mma.sync.aligned.m16n8k16.row.col.f32.bf16.bf16.f32 "         \
        "{%0,%1,%2,%3}, {%4,%5,%6,%7}, {%8,%9}, {%0,%1,%2,%3};"        \
        : "+f"(d[0]), "+f"(d[1]), "+f"(d[2]), "+f"(d[3])               \
        : "r"(a[0]), "r"(a[1]), "r"(a[2]), "r"(a[3]),                  \
          "r"(b[0]), "r"(b[1]))

__device__ __forceinline__ void split2(float x, __nv_bfloat16* h, __nv_bfloat16* l)
{
    __nv_bfloat16 hh = __float2bfloat16_rn(x);
    *h = hh;
    *l = __float2bfloat16_rn(x - __bfloat162float(hh));
}

__global__ __launch_bounds__(256) void gemm_bf16x3(
    const float* __restrict__ A, const float* __restrict__ B,
    float* __restrict__ C, int M, int N, int K)
{
    extern __shared__ __align__(16) char smraw[];
    __nv_bfloat16* sm = (__nv_bfloat16*)smraw;

    const int tid  = threadIdx.x;
    const int wid  = tid >> 5, lane = tid & 31;
    const int wm   = wid >> 2, wn = wid & 3;   // warp grid 2(m) x 4(n)
    const int lg   = lane >> 2;                // 0..7
    const int lk   = lane & 3;                 // 0..3
    const long row0 = (long)blockIdx.y * 128;
    const long col0 = (long)blockIdx.x * 128;

    const float* Aa = A + row0 * K;
    const float* Bb = B + col0;

    float acc[4][4][4];
#pragma unroll
    for (int mt = 0; mt < 4; mt++)
#pragma unroll
        for (int nt = 0; nt < 4; nt++)
#pragma unroll
            for (int e = 0; e < 4; e++) acc[mt][nt][e] = 0.f;

    // ---- prologue: fill stage 0 with kt=0 ----
    {
        __nv_bfloat16* Ah = sm;
        __nv_bfloat16* Al = sm + PLANE;
        __nv_bfloat16* Bh = sm + 2 * PLANE;
        __nv_bfloat16* Bl = sm + 3 * PLANE;
#pragma unroll
        for (int t = 0; t < 4; t++) {
            int idx = tid + t * 256;
            int r = idx >> 3, c4 = (idx & 7) << 2;
            float4 v = *(const float4*)(Aa + (long)r * K + c4);
            split2(v.x, &Ah[r * BKP + c4 + 0], &Al[r * BKP + c4 + 0]);
            split2(v.y, &Ah[r * BKP + c4 + 1], &Al[r * BKP + c4 + 1]);
            split2(v.z, &Ah[r * BKP + c4 + 2], &Al[r * BKP + c4 + 2]);
            split2(v.w, &Ah[r * BKP + c4 + 3], &Al[r * BKP + c4 + 3]);
        }
#pragma unroll
        for (int t = 0; t < 4; t++) {
            int idx = tid + t * 256;
            int r = idx >> 5, c4 = (idx & 31) << 2;     // r = k, c4 = n
            float4 v = *(const float4*)(Bb + (long)r * N + c4);
            split2(v.x, &Bh[(c4 + 0) * BKP + r], &Bl[(c4 + 0) * BKP + r]);
            split2(v.y, &Bh[(c4 + 1) * BKP + r], &Bl[(c4 + 1) * BKP + r]);
            split2(v.z, &Bh[(c4 + 2) * BKP + r], &Bl[(c4 + 2) * BKP + r]);
            split2(v.w, &Bh[(c4 + 3) * BKP + r], &Bl[(c4 + 3) * BKP + r]);
        }
    }
    __syncthreads();

    const int KT = K / 32;
    int buf = 0;
    for (int kt = 0; kt < KT; kt++) {
        float4 la[4], lb[4];
        const bool has_next = (kt + 1 < KT);
        if (has_next) {
            const int k0 = (kt + 1) * 32;
#pragma unroll
            for (int t = 0; t < 4; t++) {
                int idx = tid + t * 256;
                int r = idx >> 3, c4 = (idx & 7) << 2;
                la[t] = *(const float4*)(Aa + (long)r * K + k0 + c4);
            }
#pragma unroll
            for (int t = 0; t < 4; t++) {
                int idx = tid + t * 256;
                int r = idx >> 5, c4 = (idx & 31) << 2;
                lb[t] = *(const float4*)(Bb + (long)(k0 + r) * N + c4);
            }
        }

        const __nv_bfloat16* Ah = sm + buf * STAGE_ELEMS;
        const __nv_bfloat16* Al = Ah + PLANE;
        const __nv_bfloat16* Bh = Ah + 2 * PLANE;
        const __nv_bfloat16* Bl = Ah + 3 * PLANE;

#pragma unroll
        for (int ks = 0; ks < 32; ks += 16) {
            uint32_t ah[4][4], al[4][4], bh[4][2], bl[4][2];
#pragma unroll
            for (int mt = 0; mt < 4; mt++) {
                int r = wm * 64 + mt * 16 + lg;
                int base = r * BKP + ks + lk * 2;
                ah[mt][0] = *(const uint32_t*)&Ah[base];
                ah[mt][1] = *(const uint32_t*)&Ah[base + 8 * BKP];
                ah[mt][2] = *(const uint32_t*)&Ah[base + 8];
                ah[mt][3] = *(const uint32_t*)&Ah[base + 8 * BKP + 8];
                al[mt][0] = *(const uint32_t*)&Al[base];
                al[mt][1] = *(const uint32_t*)&Al[base + 8 * BKP];
                al[mt][2] = *(const uint32_t*)&Al[base + 8];
                al[mt][3] = *(const uint32_t*)&Al[base + 8 * BKP + 8];
            }
#pragma unroll
            for (int nt = 0; nt < 4; nt++) {
                int c = wn * 32 + nt * 8 + lg;
                int base = c * BKP + ks + lk * 2;
                bh[nt][0] = *(const uint32_t*)&Bh[base];
                bh[nt][1] = *(const uint32_t*)&Bh[base + 8];
                bl[nt][0] = *(const uint32_t*)&Bl[base];
                bl[nt][1] = *(const uint32_t*)&Bl[base + 8];
            }
            // pass 1: Ah*Bh   (each acc touched once per 16 mmas -> latency hidden)
#pragma unroll
            for (int mt = 0; mt < 4; mt++)
#pragma unroll
                for (int nt = 0; nt < 4; nt++) MMA16816(acc[mt][nt], ah[mt], bh[nt]);
            // pass 2: Ah*Bl
#pragma unroll
            for (int mt = 0; mt < 4; mt++)
#pragma unroll
                for (int nt = 0; nt < 4; nt++) MMA16816(acc[mt][nt], ah[mt], bl[nt]);
            // pass 3: Al*Bh
#pragma unroll
            for (int mt = 0; mt < 4; mt++)
#pragma unroll
                for (int nt = 0; nt < 4; nt++) MMA16816(acc[mt][nt], al[mt], bh[nt]);
        }

        if (has_next) {
            __nv_bfloat16* nAh = sm + (buf ^ 1) * STAGE_ELEMS;
            __nv_bfloat16* nAl = nAh + PLANE;
            __nv_bfloat16* nBh = nAh + 2 * PLANE;
            __nv_bfloat16* nBl = nAh + 3 * PLANE;
#pragma unroll
            for (int t = 0; t < 4; t++) {
                int idx = tid + t * 256;
                int r = idx >> 3, c4 = (idx & 7) << 2;
                split2(la[t].x, &nAh[r * BKP + c4 + 0], &nAl[r * BKP + c4 + 0]);
                split2(la[t].y, &nAh[r * BKP + c4 + 1], &nAl[r * BKP + c4 + 1]);
                split2(la[t].z, &nAh[r * BKP + c4 + 2], &nAl[r * BKP + c4 + 2]);
                split2(la[t].w, &nAh[r * BKP + c4 + 3], &nAl[r * BKP + c4 + 3]);
            }
#pragma unroll
            for (int t = 0; t < 4; t++) {
                int idx = tid + t * 256;
                int r = idx >> 5, c4 = (idx & 31) << 2;
                split2(lb[t].x, &nBh[(c4 + 0) * BKP + r], &nBl[(c4 + 0) * BKP + r]);
                split2(lb[t].y, &nBh[(c4 + 1) * BKP + r], &nBl[(c4 + 1) * BKP + r]);
                split2(lb[t].z, &nBh[(c4 + 2) * BKP + r], &nBl[(c4 + 2) * BKP + r]);
                split2(lb[t].w, &nBh[(c4 + 3) * BKP + r], &nBl[(c4 + 3) * BKP + r]);
            }
        }
        __syncthreads();
        buf ^= 1;
    }

    // ---- epilogue: write C (fp32) ----
#pragma unroll
    for (int mt = 0; mt < 4; mt++) {
        long r = row0 + wm * 64 + mt * 16 + lg;
#pragma unroll
        for (int nt = 0; nt < 4; nt++) {
            long c = col0 + wn * 32 + nt * 8 + lk * 2;
            *(float2*)&C[r * N + c]       = make_float2(acc[mt][nt][0], acc[mt][nt][1]);
            *(float2*)&C[(r + 8) * N + c] = make_float2(acc[mt][nt][2], acc[mt][nt][3]);
        }
    }
}

// =================================================================
// RoPE (reference convention: y1 = x1*c + x2*s; y2 = -x1*s + x2*c),
// applied in-place to g_q (with attention scale folded in) and g_k.
// =================================================================
__global__ void rope_kernel(const float* __restrict__ cs)
{
    const int total = S_LEN * (HQ + HKV) * (DH / 2);
    int idx = blockIdx.x * blockDim.x + threadIdx.x;
    if (idx >= total) return;
    const int d = idx & 63;
    const int h = (idx >> 6) % (HQ + HKV);
    const int s = idx / (64 * (HQ + HKV));

    const float c  = cs[s * 64 + d];
    const float sn = cs[S_LEN * 64 + s * 64 + d];

    float* base;
    float sc;
    if (h < HQ) { base = g_q + ((long)s * HQ + h) * DH;         sc = 0.08838834764831845f; } // 1/sqrt(128)
    else        { base = g_k + ((long)s * HKV + (h - HQ)) * DH; sc = 1.0f; }

    const float x1 = base[d], x2 = base[d + 64];
    base[d]      = (x1 * c + x2 * sn) * sc;
    base[d + 64] = (-x1 * sn + x2 * c) * sc;
}

// =================================================================
// Causal flash attention, fp32. One block = (64 q rows, one q head).
// 256 threads: tx = tid&15, ty = tid>>4 (4-row group).
// Score tile per thread: 4 rows x 4 cols (j = tx*4+n, 64 cols total).
// PV tile per thread:    4 rows x 8 d-cols (d = tx*8+n, 128 total).
// Dynamic smem: Qs[64][132] | Kt[128][68] | Vs[64][132] | Ps[64][68]
// NOTE: Kt row stride MUST be a multiple of 4 (float4 reads at d*stride+tx*4).
// =================================================================
#define KT_STRIDE 68
#define FLASH_SMEM ((64*132 + 128*KT_STRIDE + 64*132 + 64*68) * 4)

__global__ __launch_bounds__(256, 1) void flash_kernel()
{
    extern __shared__ float smf[];
    float* Qs = smf;                      // 64 x 132
    float* Kt = Qs + 64 * 132;            // 128 x 68  (K transposed: [d][j])
    float* Vs = Kt + 128 * KT_STRIDE;     // 64 x 132
    float* Ps = Vs + 64 * 132;            // 64 x 68   (P: [i][j])

    const int tid = threadIdx.x;
    const int tx  = tid & 15;
    const int ty  = tid >> 4;
    const int qt  = gridDim.x - 1 - blockIdx.x;  // longest blocks first
    const int h   = blockIdx.y;
    const int kvh = h >> 2;                      // G = 4
    const int q0  = qt * 64;

    // load Q tile (pre-scaled, post-RoPE)
#pragma unroll
    for (int t = 0; t < 8; t++) {
        int idx = tid + t * 256;          // 0..2047
        int r = idx >> 5;
        int c4 = (idx & 31) << 2;
        float4 v = *(const float4*)(g_q + ((long)(q0 + r) * HQ + h) * DH + c4);
        *(float4*)&Qs[r * 132 + c4] = v;
    }

    float m_i[4], l_i[4], o_acc[4][8];
#pragma unroll
    for (int m = 0; m < 4; m++) {
        m_i[m] = -INFINITY; l_i[m] = 0.f;
#pragma unroll
        for (int n = 0; n < 8; n++) o_acc[m][n] = 0.f;
    }

    for (int kt = 0; kt <= qt; kt++) {
        __syncthreads();                  // prev PV done before overwrite
        const int k0 = kt * 64;
#pragma unroll
        for (int t = 0; t < 8; t++) {
            int idx = tid + t * 256;
            int r = idx >> 5;
            int c4 = (idx & 31) << 2;
            float4 kvv = *(const float4*)(g_k + ((long)(k0 + r) * HKV + kvh) * DH + c4);
            Kt[(c4 + 0) * KT_STRIDE + r] = kvv.x;
            Kt[(c4 + 1) * KT_STRIDE + r] = kvv.y;
            Kt[(c4 + 2) * KT_STRIDE + r] = kvv.z;
            Kt[(c4 + 3) * KT_STRIDE + r] = kvv.w;
            float4 vv = *(const float4*)(g_v + ((long)(k0 + r) * HKV + kvh) * DH + c4);
            *(float4*)&Vs[r * 132 + c4] = vv;
        }
        __syncthreads();

        // ---- scores: S(4x4 per thread) = Q(row) . K(col), cols j = tx*4+n ----
        float sacc[4][4];
#pragma unroll
        for (int m = 0; m < 4; m++)
#pragma unroll
            for (int n = 0; n < 4; n++) sacc[m][n] = 0.f;

        float qbuf[4][4];
#pragma unroll 2
        for (int d4 = 0; d4 < 32; d4++) {
#pragma unroll
            for (int m = 0; m < 4; m++)
                *(float4*)qbuf[m] = *(const float4*)&Qs[(ty * 4 + m) * 132 + d4 * 4];
#pragma unroll
            for (int e = 0; e < 4; e++) {
                const int d = d4 * 4 + e;
                float kn[4];
                *(float4*)kn = *(const float4*)&Kt[d * KT_STRIDE + tx * 4];
#pragma unroll
                for (int m = 0; m < 4; m++)
#pragma unroll
                    for (int n = 0; n < 4; n++)
                        sacc[m][n] = fmaf(qbuf[m][e], kn[n], sacc[m][n]);
            }
        }

        // ---- online softmax (per row; 16 lanes with same ty share a row) ----
        const bool diag = (kt == qt);
#pragma unroll
        for (int m = 0; m < 4; m++) {
            const int ig = ty * 4 + m;    // local row; global col j = k0 + tx*4+n
            if (diag) {
#pragma unroll
                for (int n = 0; n < 4; n++)
                    if (tx * 4 + n > ig) sacc[m][n] = -INFINITY;
            }
            float mx = sacc[m][0];
#pragma unroll
            for (int n = 1; n < 4; n++) mx = fmaxf(mx, sacc[m][n]);
#pragma unroll
            for (int off = 8; off >= 1; off >>= 1)
                mx = fmaxf(mx, __shfl_xor_sync(0xffffffffu, mx, off));
            const float mnew = fmaxf(m_i[m], mx);
            const float alpha = __expf(m_i[m] - mnew);

            float rsum = 0.f;
#pragma unroll
            for (int n = 0; n < 4; n++) {
                float p = __expf(sacc[m][n] - mnew);
                sacc[m][n] = p;
                rsum += p;
            }
#pragma unroll
            for (int off = 8; off >= 1; off >>= 1)
                rsum += __shfl_xor_sync(0xffffffffu, rsum, off);

            l_i[m] = l_i[m] * alpha + rsum;
            m_i[m] = mnew;
#pragma unroll
            for (int n = 0; n < 8; n++) o_acc[m][n] *= alpha;

            *(float4*)&Ps[ig * 68 + tx * 4] =
                make_float4(sacc[m][0], sacc[m][1], sacc[m][2], sacc[m][3]);
        }
        __syncthreads();                  // Ps visible to everyone

        // ---- PV: O(4x8 per thread) += P(row,j) * V(j,d), d = tx*8+n ----
#pragma unroll 4
        for (int j = 0; j < 64; j++) {
            float pm[4];
#pragma unroll
            for (int m = 0; m < 4; m++) pm[m] = Ps[(ty * 4 + m) * 68 + j];
            float vn[8];
            const float* vp = &Vs[j * 132 + tx * 8];
            *(float4*)&vn[0] = *(const float4*)vp;
            *(float4*)&vn[4] = *(const float4*)(vp + 4);
#pragma unroll
            for (int m = 0; m < 4; m++)
#pragma unroll
                for (int n = 0; n < 8; n++)
                    o_acc[m][n] = fmaf(pm[m], vn[n], o_acc[m][n]);
        }
    }

    // epilogue: normalize and write
#pragma unroll
    for (int m = 0; m < 4; m++) {
        const float inv = 1.0f / l_i[m];
        const int row = q0 + ty * 4 + m;
        float* op = g_o + ((long)row * HQ + h) * DH + tx * 8;
        *(float4*)op       = make_float4(o_acc[m][0] * inv, o_acc[m][1] * inv,
                                         o_acc[m][2] * inv, o_acc[m][3] * inv);
        *(float4*)(op + 4) = make_float4(o_acc[m][4] * inv, o_acc[m][5] * inv,
                                         o_acc[m][6] * inv, o_acc[m][7] * inv);
    }
}

// =================================================================
extern "C" void kernel_launch(void* const* d_in, const int* in_sizes, int n_in,
                              void* d_out, int out_size)
{
    const float* x  = (const float*)d_in[0];
    const float* cs = (const float*)d_in[1];
    const float* wq = (const float*)d_in[2];
    const float* wk = (const float*)d_in[3];
    const float* wv = (const float*)d_in[4];
    const float* wo = (const float*)d_in[5];
    float* out = (float*)d_out;

    float *q, *k, *v, *o;
    cudaGetSymbolAddress((void**)&q, g_q);
    cudaGetSymbolAddress((void**)&k, g_k);
    cudaGetSymbolAddress((void**)&v, g_v);
    cudaGetSymbolAddress((void**)&o, g_o);

    cudaFuncSetAttribute((const void*)gemm_bf16x3,
                         cudaFuncAttributeMaxDynamicSharedMemorySize, GEMM_SMEM);
    cudaFuncSetAttribute((const void*)flash_kernel,
                         cudaFuncAttributeMaxDynamicSharedMemorySize, FLASH_SMEM);

    // QKV projections (tensor-core bf16x3)
    gemm_bf16x3<<<dim3(DE / 128, S_LEN / 128), 256, GEMM_SMEM>>>(x, wq, q, S_LEN, DE, DE);
    gemm_bf16x3<<<dim3((HKV * DH) / 128, S_LEN / 128), 256, GEMM_SMEM>>>(x, wk, k, S_LEN, HKV * DH, DE);
    gemm_bf16x3<<<dim3((HKV * DH) / 128, S_LEN / 128), 256, GEMM_SMEM>>>(x, wv, v, S_LEN, HKV * DH, DE);

    // RoPE (+ fold 1/sqrt(DH) into q)
    const int rope_total = S_LEN * (HQ + HKV) * (DH / 2);
    rope_kernel<<<(rope_total + 255) / 256, 256>>>(cs);

    // causal flash attention (fp32)
    flash_kernel<<<dim3(S_LEN / 64, HQ), 256, FLASH_SMEM>>>();

    // output projection (tensor-core bf16x3)
    gemm_bf16x3<<<dim3(DE / 128, S_LEN / 128), 256, GEMM_SMEM>>>(o, wo, out, S_LEN, DE, DE);
}

// round 6
// speedup vs baseline: 2.3105x; 1.3715x over previous
#include <cuda_runtime.h>
#include <cuda_bf16.h>
#include <cstdint>
#include <math.h>

#define S_LEN 2048
#define DE    4096
#define HQ    32
#define HKV   8
#define DH    128

// ---------------- scratch (no allocations allowed) ----------------
__device__ float g_q[S_LEN * HQ  * DH];   // [s][h][d], post-rope pre-scaled
__device__ float g_k[S_LEN * HKV * DH];   // [s][kh][d]
__device__ float g_v[S_LEN * HKV * DH];   // [s][kh][d]
__device__ float g_o[S_LEN * HQ  * DH];   // [s][h][d]

// bf16 hi/lo planes for tensor-core flash
__device__ __nv_bfloat16 g_qh[HQ  * S_LEN * DH];  // [h][s][d]
__device__ __nv_bfloat16 g_ql[HQ  * S_LEN * DH];
__device__ __nv_bfloat16 g_kh[HKV * S_LEN * DH];  // [kh][s][d]
__device__ __nv_bfloat16 g_kl[HKV * S_LEN * DH];
__device__ __nv_bfloat16 g_vth[HKV * DH * S_LEN]; // [kh][d][s]  (transposed)
__device__ __nv_bfloat16 g_vtl[HKV * DH * S_LEN];

#define MMA16816(d, a, b)                                              \
    asm volatile(                                                      \
        "mma.sync.aligned.m16n8k16.row.col.f32.bf16.bf16.f32 "         \
        "{%0,%1,%2,%3}, {%4,%5,%6,%7}, {%8,%9}, {%0,%1,%2,%3};"        \
        : "+f"(d[0]), "+f"(d[1]), "+f"(d[2]), "+f"(d[3])               \
        : "r"(a[0]), "r"(a[1]), "r"(a[2]), "r"(a[3]),                  \
          "r"(b[0]), "r"(b[1]))

__device__ __forceinline__ void split2(float x, __nv_bfloat16* h, __nv_bfloat16* l)
{
    __nv_bfloat16 hh = __float2bfloat16_rn(x);
    *h = hh;
    *l = __float2bfloat16_rn(x - __bfloat162float(hh));
}

// pack (a -> low half, b -> high half) as hi-plane and lo-plane bf16x2
__device__ __forceinline__ void split_pack2(float a, float b, uint32_t& ph, uint32_t& pl)
{
    __nv_bfloat162 hp = __floats2bfloat162_rn(a, b);   // .x = a (low), .y = b (high)
    ph = *(uint32_t*)&hp;
    float al = a - __bfloat162float(hp.x);
    float bl = b - __bfloat162float(hp.y);
    __nv_bfloat162 lp = __floats2bfloat162_rn(al, bl);
    pl = *(uint32_t*)&lp;
}

// =================================================================
// bf16x3 tensor-core GEMM (unchanged from R5, passing)
// =================================================================
#define BKP 34
#define PLANE (128 * BKP)
#define STAGE_ELEMS (4 * PLANE)
#define GEMM_SMEM (2 * STAGE_ELEMS * 2)

__global__ __launch_bounds__(256) void gemm_bf16x3(
    const float* __restrict__ A, const float* __restrict__ B,
    float* __restrict__ C, int M, int N, int K)
{
    extern __shared__ __align__(16) char smraw[];
    __nv_bfloat16* sm = (__nv_bfloat16*)smraw;

    const int tid  = threadIdx.x;
    const int wid  = tid >> 5, lane = tid & 31;
    const int wm   = wid >> 2, wn = wid & 3;
    const int lg   = lane >> 2;
    const int lk   = lane & 3;
    const long row0 = (long)blockIdx.y * 128;
    const long col0 = (long)blockIdx.x * 128;

    const float* Aa = A + row0 * K;
    const float* Bb = B + col0;

    float acc[4][4][4];
#pragma unroll
    for (int mt = 0; mt < 4; mt++)
#pragma unroll
        for (int nt = 0; nt < 4; nt++)
#pragma unroll
            for (int e = 0; e < 4; e++) acc[mt][nt][e] = 0.f;

    {
        __nv_bfloat16* Ah = sm;
        __nv_bfloat16* Al = sm + PLANE;
        __nv_bfloat16* Bh = sm + 2 * PLANE;
        __nv_bfloat16* Bl = sm + 3 * PLANE;
#pragma unroll
        for (int t = 0; t < 4; t++) {
            int idx = tid + t * 256;
            int r = idx >> 3, c4 = (idx & 7) << 2;
            float4 v = *(const float4*)(Aa + (long)r * K + c4);
            split2(v.x, &Ah[r * BKP + c4 + 0], &Al[r * BKP + c4 + 0]);
            split2(v.y, &Ah[r * BKP + c4 + 1], &Al[r * BKP + c4 + 1]);
            split2(v.z, &Ah[r * BKP + c4 + 2], &Al[r * BKP + c4 + 2]);
            split2(v.w, &Ah[r * BKP + c4 + 3], &Al[r * BKP + c4 + 3]);
        }
#pragma unroll
        for (int t = 0; t < 4; t++) {
            int idx = tid + t * 256;
            int r = idx >> 5, c4 = (idx & 31) << 2;
            float4 v = *(const float4*)(Bb + (long)r * N + c4);
            split2(v.x, &Bh[(c4 + 0) * BKP + r], &Bl[(c4 + 0) * BKP + r]);
            split2(v.y, &Bh[(c4 + 1) * BKP + r], &Bl[(c4 + 1) * BKP + r]);
            split2(v.z, &Bh[(c4 + 2) * BKP + r], &Bl[(c4 + 2) * BKP + r]);
            split2(v.w, &Bh[(c4 + 3) * BKP + r], &Bl[(c4 + 3) * BKP + r]);
        }
    }
    __syncthreads();

    const int KT = K / 32;
    int buf = 0;
    for (int kt = 0; kt < KT; kt++) {
        float4 la[4], lb[4];
        const bool has_next = (kt + 1 < KT);
        if (has_next) {
            const int k0 = (kt + 1) * 32;
#pragma unroll
            for (int t = 0; t < 4; t++) {
                int idx = tid + t * 256;
                int r = idx >> 3, c4 = (idx & 7) << 2;
                la[t] = *(const float4*)(Aa + (long)r * K + k0 + c4);
            }
#pragma unroll
            for (int t = 0; t < 4; t++) {
                int idx = tid + t * 256;
                int r = idx >> 5, c4 = (idx & 31) << 2;
                lb[t] = *(const float4*)(Bb + (long)(k0 + r) * N + c4);
            }
        }

        const __nv_bfloat16* Ah = sm + buf * STAGE_ELEMS;
        const __nv_bfloat16* Al = Ah + PLANE;
        const __nv_bfloat16* Bh = Ah + 2 * PLANE;
        const __nv_bfloat16* Bl = Ah + 3 * PLANE;

#pragma unroll
        for (int ks = 0; ks < 32; ks += 16) {
            uint32_t ah[4][4], al[4][4], bh[4][2], bl[4][2];
#pragma unroll
            for (int mt = 0; mt < 4; mt++) {
                int r = wm * 64 + mt * 16 + lg;
                int base = r * BKP + ks + lk * 2;
                ah[mt][0] = *(const uint32_t*)&Ah[base];
                ah[mt][1] = *(const uint32_t*)&Ah[base + 8 * BKP];
                ah[mt][2] = *(const uint32_t*)&Ah[base + 8];
                ah[mt][3] = *(const uint32_t*)&Ah[base + 8 * BKP + 8];
                al[mt][0] = *(const uint32_t*)&Al[base];
                al[mt][1] = *(const uint32_t*)&Al[base + 8 * BKP];
                al[mt][2] = *(const uint32_t*)&Al[base + 8];
                al[mt][3] = *(const uint32_t*)&Al[base + 8 * BKP + 8];
            }
#pragma unroll
            for (int nt = 0; nt < 4; nt++) {
                int c = wn * 32 + nt * 8 + lg;
                int base = c * BKP + ks + lk * 2;
                bh[nt][0] = *(const uint32_t*)&Bh[base];
                bh[nt][1] = *(const uint32_t*)&Bh[base + 8];
                bl[nt][0] = *(const uint32_t*)&Bl[base];
                bl[nt][1] = *(const uint32_t*)&Bl[base + 8];
            }
#pragma unroll
            for (int mt = 0; mt < 4; mt++)
#pragma unroll
                for (int nt = 0; nt < 4; nt++) MMA16816(acc[mt][nt], ah[mt], bh[nt]);
#pragma unroll
            for (int mt = 0; mt < 4; mt++)
#pragma unroll
                for (int nt = 0; nt < 4; nt++) MMA16816(acc[mt][nt], ah[mt], bl[nt]);
#pragma unroll
            for (int mt = 0; mt < 4; mt++)
#pragma unroll
                for (int nt = 0; nt < 4; nt++) MMA16816(acc[mt][nt], al[mt], bh[nt]);
        }

        if (has_next) {
            __nv_bfloat16* nAh = sm + (buf ^ 1) * STAGE_ELEMS;
            __nv_bfloat16* nAl = nAh + PLANE;
            __nv_bfloat16* nBh = nAh + 2 * PLANE;
            __nv_bfloat16* nBl = nAh + 3 * PLANE;
#pragma unroll
            for (int t = 0; t < 4; t++) {
                int idx = tid + t * 256;
                int r = idx >> 3, c4 = (idx & 7) << 2;
                split2(la[t].x, &nAh[r * BKP + c4 + 0], &nAl[r * BKP + c4 + 0]);
                split2(la[t].y, &nAh[r * BKP + c4 + 1], &nAl[r * BKP + c4 + 1]);
                split2(la[t].z, &nAh[r * BKP + c4 + 2], &nAl[r * BKP + c4 + 2]);
                split2(la[t].w, &nAh[r * BKP + c4 + 3], &nAl[r * BKP + c4 + 3]);
            }
#pragma unroll
            for (int t = 0; t < 4; t++) {
                int idx = tid + t * 256;
                int r = idx >> 5, c4 = (idx & 31) << 2;
                split2(lb[t].x, &nBh[(c4 + 0) * BKP + r], &nBl[(c4 + 0) * BKP + r]);
                split2(lb[t].y, &nBh[(c4 + 1) * BKP + r], &nBl[(c4 + 1) * BKP + r]);
                split2(lb[t].z, &nBh[(c4 + 2) * BKP + r], &nBl[(c4 + 2) * BKP + r]);
                split2(lb[t].w, &nBh[(c4 + 3) * BKP + r], &nBl[(c4 + 3) * BKP + r]);
            }
        }
        __syncthreads();
        buf ^= 1;
    }

#pragma unroll
    for (int mt = 0; mt < 4; mt++) {
        long r = row0 + wm * 64 + mt * 16 + lg;
#pragma unroll
        for (int nt = 0; nt < 4; nt++) {
            long c = col0 + wn * 32 + nt * 8 + lk * 2;
            *(float2*)&C[r * N + c]       = make_float2(acc[mt][nt][0], acc[mt][nt][1]);
            *(float2*)&C[(r + 8) * N + c] = make_float2(acc[mt][nt][2], acc[mt][nt][3]);
        }
    }
}

// =================================================================
// RoPE in-place on fp32 q,k (+ fold 1/sqrt(DH) into q)
// =================================================================
__global__ void rope_kernel(const float* __restrict__ cs)
{
    const int total = S_LEN * (HQ + HKV) * (DH / 2);
    int idx = blockIdx.x * blockDim.x + threadIdx.x;
    if (idx >= total) return;
    const int d = idx & 63;
    const int h = (idx >> 6) % (HQ + HKV);
    const int s = idx / (64 * (HQ + HKV));

    const float c  = cs[s * 64 + d];
    const float sn = cs[S_LEN * 64 + s * 64 + d];

    float* base;
    float sc;
    if (h < HQ) { base = g_q + ((long)s * HQ + h) * DH;         sc = 0.08838834764831845f; }
    else        { base = g_k + ((long)s * HKV + (h - HQ)) * DH; sc = 1.0f; }

    const float x1 = base[d], x2 = base[d + 64];
    base[d]      = (x1 * c + x2 * sn) * sc;
    base[d + 64] = (-x1 * sn + x2 * c) * sc;
}

// =================================================================
// Convert post-rope fp32 q/k/v into bf16 hi/lo planes (+ V transpose)
// =================================================================
__global__ void convert_kernel()
{
    const long QN = (long)S_LEN * HQ * DH;
    const long KN = (long)S_LEN * HKV * DH;
    long i = (long)blockIdx.x * blockDim.x + threadIdx.x;
    if (i < QN) {
        int d = (int)(i % DH);
        long t = i / DH;
        int h = (int)(t % HQ);
        int s = (int)(t / HQ);
        long o = ((long)h * S_LEN + s) * DH + d;
        split2(g_q[i], &g_qh[o], &g_ql[o]);
    } else if (i < QN + KN) {
        long j = i - QN;
        int d = (int)(j % DH);
        long t = j / DH;
        int kh = (int)(t % HKV);
        int s = (int)(t / HKV);
        long o = ((long)kh * S_LEN + s) * DH + d;
        split2(g_k[j], &g_kh[o], &g_kl[o]);
    } else if (i < QN + 2 * KN) {
        long j = i - QN - KN;
        int d = (int)(j % DH);
        long t = j / DH;
        int kh = (int)(t % HKV);
        int s = (int)(t / HKV);
        long o = ((long)kh * DH + d) * S_LEN + s;   // transposed
        split2(g_v[j], &g_vth[o], &g_vtl[o]);
    }
}

// =================================================================
// Tensor-core causal flash attention (bf16x3 QK and PV, fp32 softmax).
// CTA: 64 q rows x one head. 4 warps; warp w owns q rows [w*16, w*16+16),
// all 64 keys per tile. m16n8k16 mma. P stays in registers (C->A frag map).
// Smem: Qh,Ql,Kh,Kl [64][136] bf16; Vth,Vtl [128][72] bf16 ([d][key]).
// =================================================================
#define QSTR 136
#define VSTR 72
#define FL_SMEM ((4 * 64 * QSTR + 2 * 128 * VSTR) * 2)   // 106496 bytes

__global__ __launch_bounds__(128) void flash_mma_kernel()
{
    extern __shared__ __align__(16) __nv_bfloat16 sb[];
    __nv_bfloat16* sQh = sb;
    __nv_bfloat16* sQl = sQh + 64 * QSTR;
    __nv_bfloat16* sKh = sQl + 64 * QSTR;
    __nv_bfloat16* sKl = sKh + 64 * QSTR;
    __nv_bfloat16* sVh = sKl + 64 * QSTR;   // [128][72], row=d, col=key
    __nv_bfloat16* sVl = sVh + 128 * VSTR;

    const int tid  = threadIdx.x;
    const int wid  = tid >> 5, lane = tid & 31;
    const int lg   = lane >> 2, lk = lane & 3;
    const int qt   = gridDim.x - 1 - blockIdx.x;   // longest first
    const int h    = blockIdx.y;
    const int kvh  = h >> 2;
    const int q0   = qt * 64;

    // ---- load Q tile (both planes) ----
    {
        const __nv_bfloat16* gqh = g_qh + ((long)h * S_LEN + q0) * DH;
        const __nv_bfloat16* gql = g_ql + ((long)h * S_LEN + q0) * DH;
#pragma unroll
        for (int t = 0; t < 8; t++) {
            int idx = tid + t * 128;          // 1024 chunks of 8 bf16
            int r = idx >> 4, c8 = (idx & 15) << 3;
            *(uint4*)&sQh[r * QSTR + c8] = *(const uint4*)&gqh[r * DH + c8];
            *(uint4*)&sQl[r * QSTR + c8] = *(const uint4*)&gql[r * DH + c8];
        }
    }

    float m_i[2] = {-INFINITY, -INFINITY};
    float l_i[2] = {0.f, 0.f};
    float o_acc[16][4];
#pragma unroll
    for (int nt = 0; nt < 16; nt++)
#pragma unroll
        for (int e = 0; e < 4; e++) o_acc[nt][e] = 0.f;

    for (int kt = 0; kt <= qt; kt++) {
        const int k0 = kt * 64;
        __syncthreads();                      // prev tile fully consumed (also fences Q on iter 0)
        {
            const __nv_bfloat16* gkh = g_kh + ((long)kvh * S_LEN + k0) * DH;
            const __nv_bfloat16* gkl = g_kl + ((long)kvh * S_LEN + k0) * DH;
#pragma unroll
            for (int t = 0; t < 8; t++) {
                int idx = tid + t * 128;
                int r = idx >> 4, c8 = (idx & 15) << 3;
                *(uint4*)&sKh[r * QSTR + c8] = *(const uint4*)&gkh[r * DH + c8];
                *(uint4*)&sKl[r * QSTR + c8] = *(const uint4*)&gkl[r * DH + c8];
            }
            const __nv_bfloat16* gvh = g_vth + (long)kvh * DH * S_LEN + k0;
            const __nv_bfloat16* gvl = g_vtl + (long)kvh * DH * S_LEN + k0;
#pragma unroll
            for (int t = 0; t < 8; t++) {
                int idx = tid + t * 128;      // 128 d-rows x 8 chunks
                int r = idx >> 3, c8 = (idx & 7) << 3;
                *(uint4*)&sVh[r * VSTR + c8] = *(const uint4*)&gvh[(long)r * S_LEN + c8];
                *(uint4*)&sVl[r * VSTR + c8] = *(const uint4*)&gvl[(long)r * S_LEN + c8];
            }
        }
        __syncthreads();

        // ---- scores: bf16x3 QK^T. Warp: rows wid*16..+16, all 64 keys ----
        float sacc[8][4];
#pragma unroll
        for (int nt = 0; nt < 8; nt++)
#pragma unroll
            for (int e = 0; e < 4; e++) sacc[nt][e] = 0.f;

#pragma unroll
        for (int ks = 0; ks < 8; ks++) {
            uint32_t aqh[4], aql[4];
            const int ab = (wid * 16 + lg) * QSTR + ks * 16 + lk * 2;
            aqh[0] = *(const uint32_t*)&sQh[ab];
            aqh[1] = *(const uint32_t*)&sQh[ab + 8 * QSTR];
            aqh[2] = *(const uint32_t*)&sQh[ab + 8];
            aqh[3] = *(const uint32_t*)&sQh[ab + 8 * QSTR + 8];
            aql[0] = *(const uint32_t*)&sQl[ab];
            aql[1] = *(const uint32_t*)&sQl[ab + 8 * QSTR];
            aql[2] = *(const uint32_t*)&sQl[ab + 8];
            aql[3] = *(const uint32_t*)&sQl[ab + 8 * QSTR + 8];
#pragma unroll
            for (int nt = 0; nt < 8; nt++) {
                uint32_t bh[2], bl[2];
                const int bb = (nt * 8 + lg) * QSTR + ks * 16 + lk * 2;
                bh[0] = *(const uint32_t*)&sKh[bb];
                bh[1] = *(const uint32_t*)&sKh[bb + 8];
                bl[0] = *(const uint32_t*)&sKl[bb];
                bl[1] = *(const uint32_t*)&sKl[bb + 8];
                MMA16816(sacc[nt], aqh, bh);
                MMA16816(sacc[nt], aqh, bl);
                MMA16816(sacc[nt], aql, bh);
            }
        }

        // ---- causal mask on diagonal tile ----
        if (kt == qt) {
            const int r0 = wid * 16 + lg;
#pragma unroll
            for (int nt = 0; nt < 8; nt++) {
                const int c = nt * 8 + lk * 2;
                if (c     > r0)     sacc[nt][0] = -INFINITY;
                if (c + 1 > r0)     sacc[nt][1] = -INFINITY;
                if (c     > r0 + 8) sacc[nt][2] = -INFINITY;
                if (c + 1 > r0 + 8) sacc[nt][3] = -INFINITY;
            }
        }

        // ---- online softmax (rows lg and lg+8; reduce over lk quad) ----
        float mx0 = -INFINITY, mx1 = -INFINITY;
#pragma unroll
        for (int nt = 0; nt < 8; nt++) {
            mx0 = fmaxf(mx0, fmaxf(sacc[nt][0], sacc[nt][1]));
            mx1 = fmaxf(mx1, fmaxf(sacc[nt][2], sacc[nt][3]));
        }
        mx0 = fmaxf(mx0, __shfl_xor_sync(0xffffffffu, mx0, 1));
        mx0 = fmaxf(mx0, __shfl_xor_sync(0xffffffffu, mx0, 2));
        mx1 = fmaxf(mx1, __shfl_xor_sync(0xffffffffu, mx1, 1));
        mx1 = fmaxf(mx1, __shfl_xor_sync(0xffffffffu, mx1, 2));

        const float mn0 = fmaxf(m_i[0], mx0);
        const float mn1 = fmaxf(m_i[1], mx1);
        const float al0 = __expf(m_i[0] - mn0);
        const float al1 = __expf(m_i[1] - mn1);

        float rs0 = 0.f, rs1 = 0.f;
#pragma unroll
        for (int nt = 0; nt < 8; nt++) {
            float p0 = __expf(sacc[nt][0] - mn0);
            float p1 = __expf(sacc[nt][1] - mn0);
            float p2 = __expf(sacc[nt][2] - mn1);
            float p3 = __expf(sacc[nt][3] - mn1);
            sacc[nt][0] = p0; sacc[nt][1] = p1; sacc[nt][2] = p2; sacc[nt][3] = p3;
            rs0 += p0 + p1; rs1 += p2 + p3;
        }
        rs0 += __shfl_xor_sync(0xffffffffu, rs0, 1);
        rs0 += __shfl_xor_sync(0xffffffffu, rs0, 2);
        rs1 += __shfl_xor_sync(0xffffffffu, rs1, 1);
        rs1 += __shfl_xor_sync(0xffffffffu, rs1, 2);

        l_i[0] = l_i[0] * al0 + rs0;  m_i[0] = mn0;
        l_i[1] = l_i[1] * al1 + rs1;  m_i[1] = mn1;

#pragma unroll
        for (int nt = 0; nt < 16; nt++) {
            o_acc[nt][0] *= al0; o_acc[nt][1] *= al0;
            o_acc[nt][2] *= al1; o_acc[nt][3] *= al1;
        }

        // ---- PV: bf16x3, P built in registers from score C-frags ----
#pragma unroll
        for (int ks2 = 0; ks2 < 4; ks2++) {
            const int t0 = 2 * ks2, t1 = 2 * ks2 + 1;
            uint32_t ph[4], pl[4];
            split_pack2(sacc[t0][0], sacc[t0][1], ph[0], pl[0]);
            split_pack2(sacc[t0][2], sacc[t0][3], ph[1], pl[1]);
            split_pack2(sacc[t1][0], sacc[t1][1], ph[2], pl[2]);
            split_pack2(sacc[t1][2], sacc[t1][3], ph[3], pl[3]);
#pragma unroll
            for (int nt = 0; nt < 16; nt++) {
                uint32_t bh[2], bl[2];
                const int bb = (nt * 8 + lg) * VSTR + ks2 * 16 + lk * 2;
                bh[0] = *(const uint32_t*)&sVh[bb];
                bh[1] = *(const uint32_t*)&sVh[bb + 8];
                bl[0] = *(const uint32_t*)&sVl[bb];
                bl[1] = *(const uint32_t*)&sVl[bb + 8];
                MMA16816(o_acc[nt], ph, bh);
                MMA16816(o_acc[nt], ph, bl);
                MMA16816(o_acc[nt], pl, bh);
            }
        }
    }

    // ---- epilogue ----
    const float inv0 = 1.0f / l_i[0];
    const float inv1 = 1.0f / l_i[1];
    const int r0 = q0 + wid * 16 + lg;
#pragma unroll
    for (int nt = 0; nt < 16; nt++) {
        const int c = nt * 8 + lk * 2;
        *(float2*)&g_o[((long)r0 * HQ + h) * DH + c] =
            make_float2(o_acc[nt][0] * inv0, o_acc[nt][1] * inv0);
        *(float2*)&g_o[((long)(r0 + 8) * HQ + h) * DH + c] =
            make_float2(o_acc[nt][2] * inv1, o_acc[nt][3] * inv1);
    }
}

// =================================================================
extern "C" void kernel_launch(void* const* d_in, const int* in_sizes, int n_in,
                              void* d_out, int out_size)
{
    const float* x  = (const float*)d_in[0];
    const float* cs = (const float*)d_in[1];
    const float* wq = (const float*)d_in[2];
    const float* wk = (const float*)d_in[3];
    const float* wv = (const float*)d_in[4];
    const float* wo = (const float*)d_in[5];
    float* out = (float*)d_out;

    float *q, *k, *v, *o;
    cudaGetSymbolAddress((void**)&q, g_q);
    cudaGetSymbolAddress((void**)&k, g_k);
    cudaGetSymbolAddress((void**)&v, g_v);
    cudaGetSymbolAddress((void**)&o, g_o);

    cudaFuncSetAttribute((const void*)gemm_bf16x3,
                         cudaFuncAttributeMaxDynamicSharedMemorySize, GEMM_SMEM);
    cudaFuncSetAttribute((const void*)flash_mma_kernel,
                         cudaFuncAttributeMaxDynamicSharedMemorySize, FL_SMEM);

    // QKV projections (tensor-core bf16x3)
    gemm_bf16x3<<<dim3(DE / 128, S_LEN / 128), 256, GEMM_SMEM>>>(x, wq, q, S_LEN, DE, DE);
    gemm_bf16x3<<<dim3((HKV * DH) / 128, S_LEN / 128), 256, GEMM_SMEM>>>(x, wk, k, S_LEN, HKV * DH, DE);
    gemm_bf16x3<<<dim3((HKV * DH) / 128, S_LEN / 128), 256, GEMM_SMEM>>>(x, wv, v, S_LEN, HKV * DH, DE);

    // RoPE (+ fold 1/sqrt(DH) into q)
    const int rope_total = S_LEN * (HQ + HKV) * (DH / 2);
    rope_kernel<<<(rope_total + 255) / 256, 256>>>(cs);

    // split into bf16 hi/lo planes (and transpose V)
    const long conv_total = (long)S_LEN * HQ * DH + 2L * S_LEN * HKV * DH;
    convert_kernel<<<(int)((conv_total + 255) / 256), 256>>>();

    // tensor-core causal flash attention
    flash_mma_kernel<<<dim3(S_LEN / 64, HQ), 128, FL_SMEM>>>();

    // output projection (tensor-core bf16x3)
    gemm_bf16x3<<<dim3(DE / 128, S_LEN / 128), 256, GEMM_SMEM>>>(o, wo, out, S_LEN, DE, DE);
}

// round 10
// speedup vs baseline: 2.3171x; 1.0028x over previous
#include <cuda_runtime.h>
#include <cuda_bf16.h>
#include <cstdint>
#include <math.h>

#define S_LEN 2048
#define DE    4096
#define HQ    32
#define HKV   8
#define DH    128

// ---------------- scratch (no allocations allowed) ----------------
__device__ float g_q[S_LEN * HQ  * DH];   // [s][h][d], post-rope pre-scaled
__device__ float g_k[S_LEN * HKV * DH];   // [s][kh][d]
__device__ float g_v[S_LEN * HKV * DH];   // [s][kh][d]
__device__ float g_o[S_LEN * HQ  * DH];   // [s][h][d]

// flash bf16 hi/lo planes
__device__ __nv_bfloat16 g_qh[HQ  * S_LEN * DH];
__device__ __nv_bfloat16 g_ql[HQ  * S_LEN * DH];
__device__ __nv_bfloat16 g_kh[HKV * S_LEN * DH];
__device__ __nv_bfloat16 g_kl[HKV * S_LEN * DH];
__device__ __nv_bfloat16 g_vth[HKV * DH * S_LEN];
__device__ __nv_bfloat16 g_vtl[HKV * DH * S_LEN];

#define MMA16816(d, a, b)                                              \
    asm volatile(                                                      \
        "mma.sync.aligned.m16n8k16.row.col.f32.bf16.bf16.f32 "         \
        "{%0,%1,%2,%3}, {%4,%5,%6,%7}, {%8,%9}, {%0,%1,%2,%3};"        \
        : "+f"(d[0]), "+f"(d[1]), "+f"(d[2]), "+f"(d[3])               \
        : "r"(a[0]), "r"(a[1]), "r"(a[2]), "r"(a[3]),                  \
          "r"(b[0]), "r"(b[1]))

__device__ __forceinline__ void split2(float x, __nv_bfloat16* h, __nv_bfloat16* l)
{
    __nv_bfloat16 hh = __float2bfloat16_rn(x);
    *h = hh;
    *l = __float2bfloat16_rn(x - __bfloat162float(hh));
}

__device__ __forceinline__ void split_pack2(float a, float b, uint32_t& ph, uint32_t& pl)
{
    __nv_bfloat162 hp = __floats2bfloat162_rn(a, b);
    ph = *(uint32_t*)&hp;
    float al = a - __bfloat162float(hp.x);
    float bl = b - __bfloat162float(hp.y);
    __nv_bfloat162 lp = __floats2bfloat162_rn(al, bl);
    pl = *(uint32_t*)&lp;
}

// =================================================================
// bf16x3 tensor-core GEMM (R5/R6 verbatim — PROVEN)
// =================================================================
#define BKP 34
#define PLANE (128 * BKP)
#define STAGE_ELEMS (4 * PLANE)
#define GEMM_SMEM (2 * STAGE_ELEMS * 2)

__global__ __launch_bounds__(256) void gemm_bf16x3(
    const float* __restrict__ A, const float* __restrict__ B,
    float* __restrict__ C, int M, int N, int K)
{
    extern __shared__ __align__(16) char smraw[];
    __nv_bfloat16* sm = (__nv_bfloat16*)smraw;

    const int tid  = threadIdx.x;
    const int wid  = tid >> 5, lane = tid & 31;
    const int wm   = wid >> 2, wn = wid & 3;
    const int lg   = lane >> 2;
    const int lk   = lane & 3;
    const long row0 = (long)blockIdx.y * 128;
    const long col0 = (long)blockIdx.x * 128;

    const float* Aa = A + row0 * K;
    const float* Bb = B + col0;

    float acc[4][4][4];
#pragma unroll
    for (int mt = 0; mt < 4; mt++)
#pragma unroll
        for (int nt = 0; nt < 4; nt++)
#pragma unroll
            for (int e = 0; e < 4; e++) acc[mt][nt][e] = 0.f;

    {
        __nv_bfloat16* Ah = sm;
        __nv_bfloat16* Al = sm + PLANE;
        __nv_bfloat16* Bh = sm + 2 * PLANE;
        __nv_bfloat16* Bl = sm + 3 * PLANE;
#pragma unroll
        for (int t = 0; t < 4; t++) {
            int idx = tid + t * 256;
            int r = idx >> 3, c4 = (idx & 7) << 2;
            float4 v = *(const float4*)(Aa + (long)r * K + c4);
            split2(v.x, &Ah[r * BKP + c4 + 0], &Al[r * BKP + c4 + 0]);
            split2(v.y, &Ah[r * BKP + c4 + 1], &Al[r * BKP + c4 + 1]);
            split2(v.z, &Ah[r * BKP + c4 + 2], &Al[r * BKP + c4 + 2]);
            split2(v.w, &Ah[r * BKP + c4 + 3], &Al[r * BKP + c4 + 3]);
        }
#pragma unroll
        for (int t = 0; t < 4; t++) {
            int idx = tid + t * 256;
            int r = idx >> 5, c4 = (idx & 31) << 2;
            float4 v = *(const float4*)(Bb + (long)r * N + c4);
            split2(v.x, &Bh[(c4 + 0) * BKP + r], &Bl[(c4 + 0) * BKP + r]);
            split2(v.y, &Bh[(c4 + 1) * BKP + r], &Bl[(c4 + 1) * BKP + r]);
            split2(v.z, &Bh[(c4 + 2) * BKP + r], &Bl[(c4 + 2) * BKP + r]);
            split2(v.w, &Bh[(c4 + 3) * BKP + r], &Bl[(c4 + 3) * BKP + r]);
        }
    }
    __syncthreads();

    const int KT = K / 32;
    int buf = 0;
    for (int kt = 0; kt < KT; kt++) {
        float4 la[4], lb[4];
        const bool has_next = (kt + 1 < KT);
        if (has_next) {
            const int k0 = (kt + 1) * 32;
#pragma unroll
            for (int t = 0; t < 4; t++) {
                int idx = tid + t * 256;
                int r = idx >> 3, c4 = (idx & 7) << 2;
                la[t] = *(const float4*)(Aa + (long)r * K + k0 + c4);
            }
#pragma unroll
            for (int t = 0; t < 4; t++) {
                int idx = tid + t * 256;
                int r = idx >> 5, c4 = (idx & 31) << 2;
                lb[t] = *(const float4*)(Bb + (long)(k0 + r) * N + c4);
            }
        }

        const __nv_bfloat16* Ah = sm + buf * STAGE_ELEMS;
        const __nv_bfloat16* Al = Ah + PLANE;
        const __nv_bfloat16* Bh = Ah + 2 * PLANE;
        const __nv_bfloat16* Bl = Ah + 3 * PLANE;

#pragma unroll
        for (int ks = 0; ks < 32; ks += 16) {
            uint32_t ah[4][4], al[4][4], bh[4][2], bl[4][2];
#pragma unroll
            for (int mt = 0; mt < 4; mt++) {
                int r = wm * 64 + mt * 16 + lg;
                int base = r * BKP + ks + lk * 2;
                ah[mt][0] = *(const uint32_t*)&Ah[base];
                ah[mt][1] = *(const uint32_t*)&Ah[base + 8 * BKP];
                ah[mt][2] = *(const uint32_t*)&Ah[base + 8];
                ah[mt][3] = *(const uint32_t*)&Ah[base + 8 * BKP + 8];
                al[mt][0] = *(const uint32_t*)&Al[base];
                al[mt][1] = *(const uint32_t*)&Al[base + 8 * BKP];
                al[mt][2] = *(const uint32_t*)&Al[base + 8];
                al[mt][3] = *(const uint32_t*)&Al[base + 8 * BKP + 8];
            }
#pragma unroll
            for (int nt = 0; nt < 4; nt++) {
                int c = wn * 32 + nt * 8 + lg;
                int base = c * BKP + ks + lk * 2;
                bh[nt][0] = *(const uint32_t*)&Bh[base];
                bh[nt][1] = *(const uint32_t*)&Bh[base + 8];
                bl[nt][0] = *(const uint32_t*)&Bl[base];
                bl[nt][1] = *(const uint32_t*)&Bl[base + 8];
            }
#pragma unroll
            for (int mt = 0; mt < 4; mt++)
#pragma unroll
                for (int nt = 0; nt < 4; nt++) MMA16816(acc[mt][nt], ah[mt], bh[nt]);
#pragma unroll
            for (int mt = 0; mt < 4; mt++)
#pragma unroll
                for (int nt = 0; nt < 4; nt++) MMA16816(acc[mt][nt], ah[mt], bl[nt]);
#pragma unroll
            for (int mt = 0; mt < 4; mt++)
#pragma unroll
                for (int nt = 0; nt < 4; nt++) MMA16816(acc[mt][nt], al[mt], bh[nt]);
        }

        if (has_next) {
            __nv_bfloat16* nAh = sm + (buf ^ 1) * STAGE_ELEMS;
            __nv_bfloat16* nAl = nAh + PLANE;
            __nv_bfloat16* nBh = nAh + 2 * PLANE;
            __nv_bfloat16* nBl = nAh + 3 * PLANE;
#pragma unroll
            for (int t = 0; t < 4; t++) {
                int idx = tid + t * 256;
                int r = idx >> 3, c4 = (idx & 7) << 2;
                split2(la[t].x, &nAh[r * BKP + c4 + 0], &nAl[r * BKP + c4 + 0]);
                split2(la[t].y, &nAh[r * BKP + c4 + 1], &nAl[r * BKP + c4 + 1]);
                split2(la[t].z, &nAh[r * BKP + c4 + 2], &nAl[r * BKP + c4 + 2]);
                split2(la[t].w, &nAh[r * BKP + c4 + 3], &nAl[r * BKP + c4 + 3]);
            }
#pragma unroll
            for (int t = 0; t < 4; t++) {
                int idx = tid + t * 256;
                int r = idx >> 5, c4 = (idx & 31) << 2;
                split2(lb[t].x, &nBh[(c4 + 0) * BKP + r], &nBl[(c4 + 0) * BKP + r]);
                split2(lb[t].y, &nBh[(c4 + 1) * BKP + r], &nBl[(c4 + 1) * BKP + r]);
                split2(lb[t].z, &nBh[(c4 + 2) * BKP + r], &nBl[(c4 + 2) * BKP + r]);
                split2(lb[t].w, &nBh[(c4 + 3) * BKP + r], &nBl[(c4 + 3) * BKP + r]);
            }
        }
        __syncthreads();
        buf ^= 1;
    }

#pragma unroll
    for (int mt = 0; mt < 4; mt++) {
        long r = row0 + wm * 64 + mt * 16 + lg;
#pragma unroll
        for (int nt = 0; nt < 4; nt++) {
            long c = col0 + wn * 32 + nt * 8 + lk * 2;
            *(float2*)&C[r * N + c]       = make_float2(acc[mt][nt][0], acc[mt][nt][1]);
            *(float2*)&C[(r + 8) * N + c] = make_float2(acc[mt][nt][2], acc[mt][nt][3]);
        }
    }
}

// =================================================================
// RoPE in-place on fp32 q,k (+ fold 1/sqrt(DH) into q)  [R6 verbatim]
// =================================================================
__global__ void rope_kernel(const float* __restrict__ cs)
{
    const int total = S_LEN * (HQ + HKV) * (DH / 2);
    int idx = blockIdx.x * blockDim.x + threadIdx.x;
    if (idx >= total) return;
    const int d = idx & 63;
    const int h = (idx >> 6) % (HQ + HKV);
    const int s = idx / (64 * (HQ + HKV));

    const float c  = cs[s * 64 + d];
    const float sn = cs[S_LEN * 64 + s * 64 + d];

    float* base;
    float sc;
    if (h < HQ) { base = g_q + ((long)s * HQ + h) * DH;         sc = 0.08838834764831845f; }
    else        { base = g_k + ((long)s * HKV + (h - HQ)) * DH; sc = 1.0f; }

    const float x1 = base[d], x2 = base[d + 64];
    base[d]      = (x1 * c + x2 * sn) * sc;
    base[d + 64] = (-x1 * sn + x2 * c) * sc;
}

// =================================================================
// Convert post-rope fp32 q/k/v into bf16 hi/lo planes  [R6 verbatim]
// =================================================================
__global__ void convert_kernel()
{
    const long QN = (long)S_LEN * HQ * DH;
    const long KN = (long)S_LEN * HKV * DH;
    long i = (long)blockIdx.x * blockDim.x + threadIdx.x;
    if (i < QN) {
        int d = (int)(i % DH);
        long t = i / DH;
        int h = (int)(t % HQ);
        int s = (int)(t / HQ);
        long o = ((long)h * S_LEN + s) * DH + d;
        split2(g_q[i], &g_qh[o], &g_ql[o]);
    } else if (i < QN + KN) {
        long j = i - QN;
        int d = (int)(j % DH);
        long t = j / DH;
        int kh = (int)(t % HKV);
        int s = (int)(t / HKV);
        long o = ((long)kh * S_LEN + s) * DH + d;
        split2(g_k[j], &g_kh[o], &g_kl[o]);
    } else if (i < QN + 2 * KN) {
        long j = i - QN - KN;
        int d = (int)(j % DH);
        long t = j / DH;
        int kh = (int)(t % HKV);
        int s = (int)(t / HKV);
        long o = ((long)kh * DH + d) * S_LEN + s;
        split2(g_v[j], &g_vth[o], &g_vtl[o]);
    }
}

// =================================================================
// Tensor-core causal flash attention — 128-row q-tiles, 8 warps.
// Warp w owns q rows [q0 + w*16, q0 + w*16 + 16). K tiles of 64 keys.
// Per-warp compute skip for tiles above the warp's rows; global-index
// causal mask. All per-warp math identical to the R6-proven kernel.
// Smem: Qh,Ql [128][136] | Kh,Kl [64][136] | Vh,Vl [128][72]  (bf16)
// =================================================================
#define QSTR 136
#define VSTR 72
#define FL_SMEM ((2 * 128 * QSTR + 2 * 64 * QSTR + 2 * 128 * VSTR) * 2)  // 141312 B

__global__ __launch_bounds__(256) void flash_mma_kernel()
{
    extern __shared__ __align__(16) __nv_bfloat16 sb[];
    __nv_bfloat16* sQh = sb;                    // 128 x 136
    __nv_bfloat16* sQl = sQh + 128 * QSTR;      // 128 x 136
    __nv_bfloat16* sKh = sQl + 128 * QSTR;      //  64 x 136
    __nv_bfloat16* sKl = sKh + 64 * QSTR;       //  64 x 136
    __nv_bfloat16* sVh = sKl + 64 * QSTR;       // 128 x 72  ([d][key])
    __nv_bfloat16* sVl = sVh + 128 * VSTR;      // 128 x 72

    const int tid  = threadIdx.x;
    const int wid  = tid >> 5, lane = tid & 31;   // wid 0..7
    const int lg   = lane >> 2, lk = lane & 3;
    const int qt   = gridDim.x - 1 - blockIdx.x;  // longest first
    const int h    = blockIdx.y;
    const int kvh  = h >> 2;
    const int q0   = qt * 128;
    const int wr0  = q0 + wid * 16;               // warp's first global row

    // ---- load Q tile (128 rows, both planes) ----
    {
        const __nv_bfloat16* gqh = g_qh + ((long)h * S_LEN + q0) * DH;
        const __nv_bfloat16* gql = g_ql + ((long)h * S_LEN + q0) * DH;
#pragma unroll
        for (int t = 0; t < 8; t++) {
            int idx = tid + t * 256;          // 0..2047 uint4 chunks
            int r = idx >> 4, c8 = (idx & 15) << 3;
            *(uint4*)&sQh[r * QSTR + c8] = *(const uint4*)&gqh[r * DH + c8];
            *(uint4*)&sQl[r * QSTR + c8] = *(const uint4*)&gql[r * DH + c8];
        }
    }

    float m_i[2] = {-INFINITY, -INFINITY};
    float l_i[2] = {0.f, 0.f};
    float o_acc[16][4];
#pragma unroll
    for (int nt = 0; nt < 16; nt++)
#pragma unroll
        for (int e = 0; e < 4; e++) o_acc[nt][e] = 0.f;

    const int KT = 2 * qt + 2;                // k tiles covering keys <= q0+127
    for (int kt = 0; kt < KT; kt++) {
        const int k0 = kt * 64;
        __syncthreads();                      // prev tile fully consumed
        {
            const __nv_bfloat16* gkh = g_kh + ((long)kvh * S_LEN + k0) * DH;
            const __nv_bfloat16* gkl = g_kl + ((long)kvh * S_LEN + k0) * DH;
#pragma unroll
            for (int t = 0; t < 4; t++) {
                int idx = tid + t * 256;      // 0..1023 chunks (64 rows x 16)
                int r = idx >> 4, c8 = (idx & 15) << 3;
                *(uint4*)&sKh[r * QSTR + c8] = *(const uint4*)&gkh[r * DH + c8];
                *(uint4*)&sKl[r * QSTR + c8] = *(const uint4*)&gkl[r * DH + c8];
            }
            const __nv_bfloat16* gvh = g_vth + (long)kvh * DH * S_LEN + k0;
            const __nv_bfloat16* gvl = g_vtl + (long)kvh * DH * S_LEN + k0;
#pragma unroll
            for (int t = 0; t < 4; t++) {
                int idx = tid + t * 256;      // 128 d-rows x 8 chunks
                int r = idx >> 3, c8 = (idx & 7) << 3;
                *(uint4*)&sVh[r * VSTR + c8] = *(const uint4*)&gvh[(long)r * S_LEN + c8];
                *(uint4*)&sVl[r * VSTR + c8] = *(const uint4*)&gvl[(long)r * S_LEN + c8];
            }
        }
        __syncthreads();

        if (k0 <= wr0 + 15) {                 // warp has rows >= some keys here
            // ---- scores: bf16x3 QK^T ----
            float sacc[8][4];
#pragma unroll
            for (int nt = 0; nt < 8; nt++)
#pragma unroll
                for (int e = 0; e < 4; e++) sacc[nt][e] = 0.f;

#pragma unroll
            for (int ks = 0; ks < 8; ks++) {
                uint32_t aqh[4], aql[4];
                const int ab = (wid * 16 + lg) * QSTR + ks * 16 + lk * 2;
                aqh[0] = *(const uint32_t*)&sQh[ab];
                aqh[1] = *(const uint32_t*)&sQh[ab + 8 * QSTR];
                aqh[2] = *(const uint32_t*)&sQh[ab + 8];
                aqh[3] = *(const uint32_t*)&sQh[ab + 8 * QSTR + 8];
                aql[0] = *(const uint32_t*)&sQl[ab];
                aql[1] = *(const uint32_t*)&sQl[ab + 8 * QSTR];
                aql[2] = *(const uint32_t*)&sQl[ab + 8];
                aql[3] = *(const uint32_t*)&sQl[ab + 8 * QSTR + 8];
#pragma unroll
                for (int nt = 0; nt < 8; nt++) {
                    uint32_t bh[2], bl[2];
                    const int bb = (nt * 8 + lg) * QSTR + ks * 16 + lk * 2;
                    bh[0] = *(const uint32_t*)&sKh[bb];
                    bh[1] = *(const uint32_t*)&sKh[bb + 8];
                    bl[0] = *(const uint32_t*)&sKl[bb];
                    bl[1] = *(const uint32_t*)&sKl[bb + 8];
                    MMA16816(sacc[nt], aqh, bh);
                    MMA16816(sacc[nt], aqh, bl);
                    MMA16816(sacc[nt], aql, bh);
                }
            }

            // ---- causal mask (global indices) ----
            if (k0 + 63 > wr0) {
                const int rg0 = wr0 + lg, rg1 = wr0 + lg + 8;
#pragma unroll
                for (int nt = 0; nt < 8; nt++) {
                    const int j = k0 + nt * 8 + lk * 2;
                    if (j     > rg0) sacc[nt][0] = -INFINITY;
                    if (j + 1 > rg0) sacc[nt][1] = -INFINITY;
                    if (j     > rg1) sacc[nt][2] = -INFINITY;
                    if (j + 1 > rg1) sacc[nt][3] = -INFINITY;
                }
            }

            // ---- online softmax (rows lg, lg+8; reduce over lk quad) ----
            float mx0 = -INFINITY, mx1 = -INFINITY;
#pragma unroll
            for (int nt = 0; nt < 8; nt++) {
                mx0 = fmaxf(mx0, fmaxf(sacc[nt][0], sacc[nt][1]));
                mx1 = fmaxf(mx1, fmaxf(sacc[nt][2], sacc[nt][3]));
            }
            mx0 = fmaxf(mx0, __shfl_xor_sync(0xffffffffu, mx0, 1));
            mx0 = fmaxf(mx0, __shfl_xor_sync(0xffffffffu, mx0, 2));
            mx1 = fmaxf(mx1, __shfl_xor_sync(0xffffffffu, mx1, 1));
            mx1 = fmaxf(mx1, __shfl_xor_sync(0xffffffffu, mx1, 2));

            const float mn0 = fmaxf(m_i[0], mx0);
            const float mn1 = fmaxf(m_i[1], mx1);
            const float al0 = __expf(m_i[0] - mn0);
            const float al1 = __expf(m_i[1] - mn1);

            float rs0 = 0.f, rs1 = 0.f;
#pragma unroll
            for (int nt = 0; nt < 8; nt++) {
                float p0 = __expf(sacc[nt][0] - mn0);
                float p1 = __expf(sacc[nt][1] - mn0);
                float p2 = __expf(sacc[nt][2] - mn1);
                float p3 = __expf(sacc[nt][3] - mn1);
                sacc[nt][0] = p0; sacc[nt][1] = p1; sacc[nt][2] = p2; sacc[nt][3] = p3;
                rs0 += p0 + p1; rs1 += p2 + p3;
            }
            rs0 += __shfl_xor_sync(0xffffffffu, rs0, 1);
            rs0 += __shfl_xor_sync(0xffffffffu, rs0, 2);
            rs1 += __shfl_xor_sync(0xffffffffu, rs1, 1);
            rs1 += __shfl_xor_sync(0xffffffffu, rs1, 2);

            l_i[0] = l_i[0] * al0 + rs0;  m_i[0] = mn0;
            l_i[1] = l_i[1] * al1 + rs1;  m_i[1] = mn1;

#pragma unroll
            for (int nt = 0; nt < 16; nt++) {
                o_acc[nt][0] *= al0; o_acc[nt][1] *= al0;
                o_acc[nt][2] *= al1; o_acc[nt][3] *= al1;
            }

            // ---- PV: bf16x3, P built in registers ----
#pragma unroll
            for (int ks2 = 0; ks2 < 4; ks2++) {
                const int t0 = 2 * ks2, t1 = 2 * ks2 + 1;
                uint32_t ph[4], pl[4];
                split_pack2(sacc[t0][0], sacc[t0][1], ph[0], pl[0]);
                split_pack2(sacc[t0][2], sacc[t0][3], ph[1], pl[1]);
                split_pack2(sacc[t1][0], sacc[t1][1], ph[2], pl[2]);
                split_pack2(sacc[t1][2], sacc[t1][3], ph[3], pl[3]);
#pragma unroll
                for (int nt = 0; nt < 16; nt++) {
                    uint32_t bh[2], bl[2];
                    const int bb = (nt * 8 + lg) * VSTR + ks2 * 16 + lk * 2;
                    bh[0] = *(const uint32_t*)&sVh[bb];
                    bh[1] = *(const uint32_t*)&sVh[bb + 8];
                    bl[0] = *(const uint32_t*)&sVl[bb];
                    bl[1] = *(const uint32_t*)&sVl[bb + 8];
                    MMA16816(o_acc[nt], ph, bh);
                    MMA16816(o_acc[nt], ph, bl);
                    MMA16816(o_acc[nt], pl, bh);
                }
            }
        }
    }

    // ---- epilogue ----
    const float inv0 = 1.0f / l_i[0];
    const float inv1 = 1.0f / l_i[1];
    const int r0 = wr0 + lg;
#pragma unroll
    for (int nt = 0; nt < 16; nt++) {
        const int c = nt * 8 + lk * 2;
        *(float2*)&g_o[((long)r0 * HQ + h) * DH + c] =
            make_float2(o_acc[nt][0] * inv0, o_acc[nt][1] * inv0);
        *(float2*)&g_o[((long)(r0 + 8) * HQ + h) * DH + c] =
            make_float2(o_acc[nt][2] * inv1, o_acc[nt][3] * inv1);
    }
}

// =================================================================
extern "C" void kernel_launch(void* const* d_in, const int* in_sizes, int n_in,
                              void* d_out, int out_size)
{
    const float* x  = (const float*)d_in[0];
    const float* cs = (const float*)d_in[1];
    const float* wq = (const float*)d_in[2];
    const float* wk = (const float*)d_in[3];
    const float* wv = (const float*)d_in[4];
    const float* wo = (const float*)d_in[5];
    float* out = (float*)d_out;

    float *q, *k, *v, *o;
    cudaGetSymbolAddress((void**)&q, g_q);
    cudaGetSymbolAddress((void**)&k, g_k);
    cudaGetSymbolAddress((void**)&v, g_v);
    cudaGetSymbolAddress((void**)&o, g_o);

    cudaFuncSetAttribute((const void*)gemm_bf16x3,
                         cudaFuncAttributeMaxDynamicSharedMemorySize, GEMM_SMEM);
    cudaFuncSetAttribute((const void*)flash_mma_kernel,
                         cudaFuncAttributeMaxDynamicSharedMemorySize, FL_SMEM);

    // QKV projections (tensor-core bf16x3)
    gemm_bf16x3<<<dim3(DE / 128, S_LEN / 128), 256, GEMM_SMEM>>>(x, wq, q, S_LEN, DE, DE);
    gemm_bf16x3<<<dim3((HKV * DH) / 128, S_LEN / 128), 256, GEMM_SMEM>>>(x, wk, k, S_LEN, HKV * DH, DE);
    gemm_bf16x3<<<dim3((HKV * DH) / 128, S_LEN / 128), 256, GEMM_SMEM>>>(x, wv, v, S_LEN, HKV * DH, DE);

    // RoPE (+ fold 1/sqrt(DH) into q)
    const int rope_total = S_LEN * (HQ + HKV) * (DH / 2);
    rope_kernel<<<(rope_total + 255) / 256, 256>>>(cs);

    // split into bf16 hi/lo planes (and transpose V)
    const long conv_total = (long)S_LEN * HQ * DH + 2L * S_LEN * HKV * DH;
    convert_kernel<<<(int)((conv_total + 255) / 256), 256>>>();

    // tensor-core causal flash attention (128-row q tiles)
    flash_mma_kernel<<<dim3(S_LEN / 128, HQ), 256, FL_SMEM>>>();

    // output projection (tensor-core bf16x3)
    gemm_bf16x3<<<dim3(DE / 128, S_LEN / 128), 256, GEMM_SMEM>>>(o, wo, out, S_LEN, DE, DE);
}